// round 6
// baseline (speedup 1.0000x reference)
#include <cuda_runtime.h>
#include <cuda_fp16.h>
#include <cstdint>

// ======================= constants =======================
#define D_FEAT  64
#define KNN     5
#define KH      192            // 3 x 64 fp16 (hi/lo cross-term expansion)
#define TPB     256
#define NB      79             // number of 128-row blocks
#define NPAIR   (NB * (NB + 1) / 2)   // 3160 upper-triangular block pairs
#define NSLOT   NB
#define NPADR   (NB * 128)     // 10112
#define NEG_INF (-3.402823466e38f)

// smem layout (bytes): row stride 400 (200 halfs) -> ldmatrix conflict-free
#define SAB      400
#define SM_A     0            // 128 x 400 = 51200
#define SM_B     51200        // 128 x 400 = 51200
#define SM_SQA   102400       // 128 floats
#define SM_SQB   102912       // 128 floats
#define SMEM_DYN 103424
// overlays (A/B regions reused after the MMA):
#define SM_MV    0                    // 128*8*5 floats = 20480
#define SM_MI    20480                // 128*8*5 ints
#define TSTRIDE  133                  // words; 133*4B rows -> conflict-free col scans
#define SM_CLV   69632                // 128*5 floats (col-side half-lists)
#define SM_CLI   72192                // 128*5 ints

// ======================= device scratch (static; no allocs) =======================
__device__ __half g_xa[(size_t)NPADR * KH];   // [hi, lo, hi]
__device__ __half g_xb[(size_t)NPADR * KH];   // [hi, hi, lo]
__device__ float  g_sq[NPADR];
__device__ float  g_topv[(size_t)NPADR * NSLOT * KNN];
__device__ int    g_topi[(size_t)NPADR * NSLOT * KNN];

// ======================= baseline-ISA PTX helpers (NO tcgen05) =======================
__device__ __forceinline__ uint32_t smem_to_u32(const void* p) {
    uint32_t a;
    asm("{ .reg .u64 t; cvta.to.shared.u64 t, %1; cvt.u32.u64 %0, t; }" : "=r"(a) : "l"(p));
    return a;
}
__device__ __forceinline__ void cp16(uint32_t dst, const void* src) {
    asm volatile("cp.async.cg.shared.global [%0], [%1], 16;" :: "r"(dst), "l"(src));
}
#define CP_COMMIT() asm volatile("cp.async.commit_group;" ::: "memory")
#define CP_WAIT(n)  asm volatile("cp.async.wait_group %0;" :: "n"(n) : "memory")

__device__ __forceinline__ void ldsm_x4(uint32_t* r, uint32_t addr) {
    asm volatile("ldmatrix.sync.aligned.m8n8.x4.shared.b16 {%0,%1,%2,%3}, [%4];"
                 : "=r"(r[0]), "=r"(r[1]), "=r"(r[2]), "=r"(r[3]) : "r"(addr));
}
__device__ __forceinline__ void mma16816(float* c, const uint32_t* a, const uint32_t* b) {
    asm volatile("mma.sync.aligned.m16n8k16.row.col.f32.f16.f16.f32 "
                 "{%0,%1,%2,%3}, {%4,%5,%6,%7}, {%8,%9}, {%0,%1,%2,%3};"
                 : "+f"(c[0]), "+f"(c[1]), "+f"(c[2]), "+f"(c[3])
                 : "r"(a[0]), "r"(a[1]), "r"(a[2]), "r"(a[3]), "r"(b[0]), "r"(b[1]));
}

// ======================= top-k =======================
__device__ __forceinline__ bool knn_better(float v, int i, float v2, int i2) {
    return (v > v2) || (v == v2 && i < i2);
}
__device__ __forceinline__ void topk_insert5(float* tv, int* ti, float v, int i) {
    bool cont = true;
#pragma unroll
    for (int s = 0; s < KNN; ++s) {
        bool up = (s < KNN - 1) && knn_better(v, i, tv[s + 1], ti[s + 1]);
        if (cont) {
            if (up) { tv[s] = tv[s + 1]; ti[s] = ti[s + 1]; }
            else    { tv[s] = v;          ti[s] = i; cont = false; }
        }
    }
}

// ======================= prep: element-parallel fp16 split + warp-reduced norms ======
__global__ void prep_kernel(const float* __restrict__ x, int N) {
    const int idx = blockIdx.x * blockDim.x + threadIdx.x;
    if (idx >= NPADR * 16) return;
    const int i  = idx >> 4;
    const int kq = idx & 15;
    const int k  = kq * 4;

    float4 v4 = make_float4(0.f, 0.f, 0.f, 0.f);
    if (i < N) v4 = *(const float4*)(x + (size_t)i * D_FEAT + k);

    __half h[4], l[4];
    const float vv[4] = {v4.x, v4.y, v4.z, v4.w};
    float psum = 0.f;
#pragma unroll
    for (int e = 0; e < 4; ++e) {
        psum += vv[e] * vv[e];
        h[e] = __float2half_rn(vv[e]);
        l[e] = __float2half_rn(vv[e] - __half2float(h[e]));
    }
    uint2 hp, lp;
    hp.x = __half_as_ushort(h[0]) | ((uint32_t)__half_as_ushort(h[1]) << 16);
    hp.y = __half_as_ushort(h[2]) | ((uint32_t)__half_as_ushort(h[3]) << 16);
    lp.x = __half_as_ushort(l[0]) | ((uint32_t)__half_as_ushort(l[1]) << 16);
    lp.y = __half_as_ushort(l[2]) | ((uint32_t)__half_as_ushort(l[3]) << 16);

    __half* a = g_xa + (size_t)i * KH;
    __half* b = g_xb + (size_t)i * KH;
    *(uint2*)(a + k)       = hp;   // A: [hi, lo, hi]
    *(uint2*)(a + 64 + k)  = lp;
    *(uint2*)(a + 128 + k) = hp;
    *(uint2*)(b + k)       = hp;   // B: [hi, hi, lo]
    *(uint2*)(b + 64 + k)  = hp;
    *(uint2*)(b + 128 + k) = lp;

#pragma unroll
    for (int s = 8; s > 0; s >>= 1) psum += __shfl_xor_sync(0xffffffffu, psum, s);
    if (kq == 0) g_sq[i] = psum;
}

// ======================= one 128x128 block-pair per CTA (J >= I) =======================
__global__ __launch_bounds__(TPB, 2)
void gemm_knn_kernel(float* __restrict__ out, int N) {
    extern __shared__ __align__(16) char smem[];
    const uint32_t sb = smem_to_u32(smem);
    float* sqA = (float*)(smem + SM_SQA);
    float* sqB = (float*)(smem + SM_SQB);

    const int tid  = threadIdx.x;
    const int w    = tid >> 5;
    const int lane = tid & 31;
    const int wm   = w & 3;       // 4 M-warps (32 rows each)
    const int wn   = w >> 2;      // 2 N-warps (64 cols each)
    const int g    = lane >> 2;
    const int q    = lane & 3;

    // blockIdx.x -> upper-triangular pair (I, J)
    int p = blockIdx.x, I = 0, rem = NB;
    while (p >= rem) { p -= rem; --rem; ++I; }
    const int J = I + p;
    const int row0 = I * 128;
    const int col0 = J * 128;

    // ---- ldmatrix per-thread base offsets ----
    const uint32_t aAddr0 = sb + SM_A + (uint32_t)(wm * 32 + (lane & 15)) * SAB + ((lane >> 4) * 8) * 2;
    const uint32_t aAddr1 = aAddr0 + 16 * SAB;
    uint32_t bAddr[4];
#pragma unroll
    for (int nb2 = 0; nb2 < 4; ++nb2)
        bAddr[nb2] = sb + SM_B + (uint32_t)(wn * 64 + nb2 * 16 + ((lane >> 4) << 3) + (lane & 7)) * SAB
                     + (((lane >> 3) & 1) * 8) * 2;

    // ---- async loads: A rows (block I from g_xa), B rows (block J from g_xb) ----
    for (int idx = tid; idx < 128 * 24; idx += TPB) {
        int r = idx / 24, c = idx - r * 24;
        cp16(sb + SM_A + (uint32_t)r * SAB + c * 16,
             (const char*)(g_xa + (size_t)(row0 + r) * KH) + c * 16);
    }
    for (int idx = tid; idx < 128 * 24; idx += TPB) {
        int r = idx / 24, c = idx - r * 24;
        cp16(sb + SM_B + (uint32_t)r * SAB + c * 16,
             (const char*)(g_xb + (size_t)(col0 + r) * KH) + c * 16);
    }
    if (tid < 128) sqA[tid] = g_sq[row0 + tid];
    else           sqB[tid - 128] = g_sq[col0 + tid - 128];
    CP_COMMIT();

    // ---- zero this CTA's slice of the output while loads are in flight ----
    {
        const size_t Z   = (size_t)N * (size_t)N;
        const size_t per = (((Z + NPAIR - 1) / NPAIR) + 3) & ~(size_t)3;
        const size_t lo  = (size_t)blockIdx.x * per;
        size_t hi = lo + per; if (hi > Z) hi = Z;
        if (hi > lo) {
            for (size_t idx = lo + (size_t)tid * 4; idx + 4 <= hi; idx += (size_t)TPB * 4)
                __stcs((float4*)(out + idx), make_float4(0.f, 0.f, 0.f, 0.f));
            size_t tail = hi & ~(size_t)3;
            if (tail >= lo && (size_t)tid < (hi - tail)) __stcs(out + tail + tid, 0.f);
        }
    }

    CP_WAIT(0);
    __syncthreads();

    // ---- 128x128x192 tile: 12 k-steps, warp tile 32x64 (16 HMMA / 6 LDSM) ----
    float c[2][8][4];
#pragma unroll
    for (int mb = 0; mb < 2; ++mb)
#pragma unroll
        for (int nb = 0; nb < 8; ++nb)
#pragma unroll
            for (int e = 0; e < 4; ++e) c[mb][nb][e] = 0.f;

#pragma unroll
    for (int ks = 0; ks < 12; ++ks) {
        uint32_t a0[4], a1[4], b[4][4];
        ldsm_x4(a0, aAddr0 + ks * 32);
        ldsm_x4(a1, aAddr1 + ks * 32);
#pragma unroll
        for (int nb2 = 0; nb2 < 4; ++nb2) ldsm_x4(b[nb2], bAddr[nb2] + ks * 32);
#pragma unroll
        for (int nb2 = 0; nb2 < 4; ++nb2) {
            mma16816(c[0][nb2 * 2],     a0, &b[nb2][0]);
            mma16816(c[0][nb2 * 2 + 1], a0, &b[nb2][2]);
            mma16816(c[1][nb2 * 2],     a1, &b[nb2][0]);
            mma16816(c[1][nb2 * 2 + 1], a1, &b[nb2][2]);
        }
    }

    // ---- row-side epilogue: per-thread top-5 over 64 values (4 rows x 16 cols) ----
    float tv[4][KNN]; int ti[4][KNN]; float sa0[4];
#pragma unroll
    for (int mb = 0; mb < 2; ++mb)
#pragma unroll
        for (int rr = 0; rr < 2; ++rr) {
            const int li = mb * 2 + rr;
            sa0[li] = sqA[wm * 32 + mb * 16 + rr * 8 + g];
#pragma unroll
            for (int m = 0; m < KNN; ++m) { tv[li][m] = NEG_INF; ti[li][m] = 0x7fffffff; }
        }
#pragma unroll
    for (int nb = 0; nb < 8; ++nb)
#pragma unroll
        for (int e0 = 0; e0 < 2; ++e0) {
            const int cl = wn * 64 + nb * 8 + q * 2 + e0;
            const float sb_ = sqB[cl];
            const int gc = col0 + cl;
#pragma unroll
            for (int mb = 0; mb < 2; ++mb)
#pragma unroll
                for (int rr = 0; rr < 2; ++rr) {
                    const int li = mb * 2 + rr;
                    const float d = (2.f * c[mb][nb][rr * 2 + e0] - sa0[li]) - sb_;
                    if (gc < N && knn_better(d, gc, tv[li][0], ti[li][0]))
                        topk_insert5(tv[li], ti[li], d, gc);
                }
        }

    // ---- in-CTA row merge: 8 contributor lists per row -> slot J ----
    __syncthreads();   // all ldmatrix reads done; safe to overlay A region
    float* mvs = (float*)(smem + SM_MV);
    int*   mis = (int*)(smem + SM_MI);
#pragma unroll
    for (int mb = 0; mb < 2; ++mb)
#pragma unroll
        for (int rr = 0; rr < 2; ++rr) {
            const int li   = mb * 2 + rr;
            const int rloc = wm * 32 + mb * 16 + rr * 8 + g;
            const int slot = wn * 4 + q;
            const int base = (rloc * 8 + slot) * KNN;
#pragma unroll
            for (int m = 0; m < KNN; ++m) { mvs[base + m] = tv[li][m]; mis[base + m] = ti[li][m]; }
        }
    __syncthreads();
    if (tid < 128) {
        float mv[KNN]; int mi[KNN];
#pragma unroll
        for (int m = 0; m < KNN; ++m) { mv[m] = NEG_INF; mi[m] = 0x7fffffff; }
        for (int s = 0; s < 8; ++s) {
#pragma unroll
            for (int m = 0; m < KNN; ++m) {
                float v = mvs[(tid * 8 + s) * KNN + m];
                int   j = mis[(tid * 8 + s) * KNN + m];
                if (j < N && knn_better(v, j, mv[0], mi[0])) topk_insert5(mv, mi, v, j);
            }
        }
        const size_t base = ((size_t)(row0 + tid) * NSLOT + J) * KNN;
#pragma unroll
        for (int m = 0; m < KNN; ++m) { g_topv[base + m] = mv[m]; g_topi[base + m] = mi[m]; }
    }

    // ---- col-side (off-diagonal tiles only): transpose via smem, harvest slot I ----
    if (J > I) {
        __syncthreads();   // row-merge readers done; overlay T over mvs/mis
        float* T = (float*)smem;
#pragma unroll
        for (int mb = 0; mb < 2; ++mb)
#pragma unroll
            for (int nb = 0; nb < 8; ++nb)
#pragma unroll
                for (int rr = 0; rr < 2; ++rr)
#pragma unroll
                    for (int e0 = 0; e0 < 2; ++e0) {
                        const int cl = wn * 64 + nb * 8 + q * 2 + e0;
                        const int rl = wm * 32 + mb * 16 + rr * 8 + g;
                        T[cl * TSTRIDE + rl] = c[mb][nb][rr * 2 + e0];
                    }
        __syncthreads();

        const int col  = tid & 127;
        const int half = tid >> 7;
        const float sbj = sqB[col];
        float mv[KNN]; int mi[KNN];
#pragma unroll
        for (int m = 0; m < KNN; ++m) { mv[m] = NEG_INF; mi[m] = 0x7fffffff; }
#pragma unroll 4
        for (int i2 = 0; i2 < 64; ++i2) {
            const int rl = half * 64 + i2;
            const float f = T[col * TSTRIDE + rl];
            const float d = (2.f * f - sbj) - sqA[rl];
            const int gi = row0 + rl;
            if (gi < N && knn_better(d, gi, mv[0], mi[0])) topk_insert5(mv, mi, d, gi);
        }
        float* clv = (float*)(smem + SM_CLV);
        int*   cli = (int*)(smem + SM_CLI);
        if (half) {
#pragma unroll
            for (int m = 0; m < KNN; ++m) { clv[col * KNN + m] = mv[m]; cli[col * KNN + m] = mi[m]; }
        }
        __syncthreads();
        if (!half) {
#pragma unroll
            for (int m = 0; m < KNN; ++m) {
                float v = clv[col * KNN + m];
                int   j = cli[col * KNN + m];
                if (j < N && knn_better(v, j, mv[0], mi[0])) topk_insert5(mv, mi, v, j);
            }
            const size_t base = ((size_t)(col0 + col) * NSLOT + I) * KNN;
#pragma unroll
            for (int m = 0; m < KNN; ++m) { g_topv[base + m] = mv[m]; g_topi[base + m] = mi[m]; }
        }
    }
}

// ======================= final merge across 79 slots + symmetric scatter =======================
__global__ void merge_scatter_kernel(float* __restrict__ out, int N) {
    int i = blockIdx.x * blockDim.x + threadIdx.x;
    if (i >= N) return;
    float mv[KNN]; int mi[KNN];
#pragma unroll
    for (int m = 0; m < KNN; ++m) { mv[m] = NEG_INF; mi[m] = 0x7fffffff; }
    const size_t base0 = (size_t)i * NSLOT * KNN;
    for (int s = 0; s < NSLOT; ++s) {
#pragma unroll
        for (int m = 0; m < KNN; ++m) {
            float v = g_topv[base0 + s * KNN + m];
            int   j = g_topi[base0 + s * KNN + m];
            if (j < N && knn_better(v, j, mv[0], mi[0])) topk_insert5(mv, mi, v, j);
        }
    }
    // self (d~0) is always the row max; reference zeroes the diagonal -> skip j == i.
#pragma unroll
    for (int m = 0; m < KNN; ++m) {
        const int j = mi[m]; const float v = mv[m];
        if (j < N && j != i) {
            atomicAdd(out + (size_t)i * N + j, v);
            atomicAdd(out + (size_t)j * N + i, v);
        }
    }
}

// ======================= launch =======================
extern "C" void kernel_launch(void* const* d_in, const int* in_sizes, int n_in,
                              void* d_out, int out_size) {
    const float* x = (const float*)d_in[0];
    const int N = in_sizes[0] / D_FEAT;   // 10000 here (<= NPADR)
    float* out = (float*)d_out;

    cudaFuncSetAttribute(gemm_knn_kernel, cudaFuncAttributeMaxDynamicSharedMemorySize, SMEM_DYN);

    prep_kernel<<<(NPADR * 16 + 255) / 256, 256>>>(x, N);
    gemm_knn_kernel<<<NPAIR, TPB, SMEM_DYN>>>(out, N);
    merge_scatter_kernel<<<(N + 255) / 256, 256>>>(out, N);
}